// round 6
// baseline (speedup 1.0000x reference)
#include <cuda_runtime.h>
#include <cuda_bf16.h>
#include <cstdint>
#include <cstddef>

// Problem constants
#define NWIN   4096
#define TT     49
#define DIM    384
#define HEADS  12
#define HD     32
#define NQKV   1152
#define MROWS  (NWIN * TT)            // 200704
#define SCALE  0.17677669529663687f
#define EPS    1e-6f

// GEMM tiling: BM=BN=128, BK=64
#define AST    72                     // smem row stride (bf16), 144 B
#define STAGEB (128 * AST * 2)        // 18432 B per stage per operand
#define GEMM_SMEM (4 * STAGEB)        // 73728 B (A and B, 2 stages)

// Attention smem: k/v for 2 heads
#define KST    36                     // fp32 row stride
#define ATT_SMEM (2 * 2 * TT * KST * 4)   // 56448 B

// ---------------------------------------------------------------------------
// Scratch (device globals; no allocations allowed)
// ---------------------------------------------------------------------------
__device__ float         g_qkv[(size_t)MROWS * NQKV];   // 925 MB fp32
__device__ __nv_bfloat16 g_xhi[(size_t)MROWS * DIM];
__device__ __nv_bfloat16 g_xlo[(size_t)MROWS * DIM];
__device__ __nv_bfloat16 g_chi[(size_t)MROWS * DIM];
__device__ __nv_bfloat16 g_clo[(size_t)MROWS * DIM];
__device__ __nv_bfloat16 g_whi[NQKV * DIM];
__device__ __nv_bfloat16 g_wlo[NQKV * DIM];
__device__ __nv_bfloat16 g_phi[DIM * DIM];
__device__ __nv_bfloat16 g_plo[DIM * DIM];
__device__ float         g_biasg[HEADS * TT * TT];

// ---------------------------------------------------------------------------
// PTX helpers (baseline sm_80+ ISA only — tcgen05 rejected by this toolchain)
// ---------------------------------------------------------------------------
__device__ __forceinline__ uint32_t smem_u32(const void* p) {
    uint32_t a;
    asm("{ .reg .u64 t; cvta.to.shared.u64 t, %1; cvt.u32.u64 %0, t; }"
        : "=r"(a) : "l"(p));
    return a;
}
__device__ __forceinline__ void cp_async16(uint32_t dst, const void* src) {
    asm volatile("cp.async.cg.shared.global [%0], [%1], 16;"
                 :: "r"(dst), "l"(src) : "memory");
}
__device__ __forceinline__ void ldsm4(uint32_t& r0, uint32_t& r1,
                                      uint32_t& r2, uint32_t& r3, uint32_t a) {
    asm volatile("ldmatrix.sync.aligned.m8n8.x4.shared.b16 {%0,%1,%2,%3}, [%4];"
                 : "=r"(r0), "=r"(r1), "=r"(r2), "=r"(r3) : "r"(a));
}
__device__ __forceinline__ void mma16816(float* d, const uint32_t* a,
                                         const uint32_t* b) {
    asm volatile(
        "mma.sync.aligned.m16n8k16.row.col.f32.bf16.bf16.f32 "
        "{%0,%1,%2,%3}, {%4,%5,%6,%7}, {%8,%9}, {%0,%1,%2,%3};"
        : "+f"(d[0]), "+f"(d[1]), "+f"(d[2]), "+f"(d[3])
        : "r"(a[0]), "r"(a[1]), "r"(a[2]), "r"(a[3]), "r"(b[0]), "r"(b[1]));
}

// ---------------------------------------------------------------------------
// HMMA GEMM: C = Ahi*Bhi + Ahi*Blo + Alo*Bhi (+bias). fp32 accum.
// BM=BN=128, BK=64, 8 warps (2x4), warp tile 64x32, m16n8k16.
// cp.async double-buffered; dynamic smem (74 KB).
// ---------------------------------------------------------------------------
template<bool ADD_BIAS>
__global__ __launch_bounds__(256, 2)
void gemm_hmma3(const __nv_bfloat16* __restrict__ Ah,
                const __nv_bfloat16* __restrict__ Al,
                const __nv_bfloat16* __restrict__ Bh,
                const __nv_bfloat16* __restrict__ Bl,
                const float* __restrict__ bias, float* __restrict__ C,
                int M, int N, int K) {
    extern __shared__ __nv_bfloat16 smb[];
    const uint32_t sA = smem_u32(smb);                 // [2][128*AST]
    const uint32_t sB = sA + 2 * STAGEB;

    const int tid  = threadIdx.x;
    const int wid  = tid >> 5, lane = tid & 31;
    const int bm   = blockIdx.y * 128, bn = blockIdx.x * 128;
    const int wm   = (wid >> 2) * 64,  wn = (wid & 3) * 32;

    float acc[4][4][4];
#pragma unroll
    for (int i = 0; i < 4; i++)
#pragma unroll
        for (int j = 0; j < 4; j++)
#pragma unroll
            for (int r = 0; r < 4; r++) acc[i][j][r] = 0.f;

    const __nv_bfloat16* Aps[3] = {Ah, Ah, Al};
    const __nv_bfloat16* Bps[3] = {Bh, Bl, Bh};
    const int nkc = K >> 6;          // 6 for K=384
    const int nch = 3 * nkc;         // 18

    // loader: 1024 16B-lines per operand / 256 threads = 4 each
    const int lrow = tid >> 3;       // base row 0..31
    const int lhf  = tid & 7;        // 16B-half within 128B K-slice

    // ldmatrix / B-frag lane coords
    const int m_l  = (lane & 7) + ((lane >> 3) & 1) * 8;
    const int kb_l = (lane >> 4) * 8;
    const int bn_l = lane >> 2;
    const int bk_l = (lane & 3) * 2;

#define PREFETCH(c, s)                                                          \
    do {                                                                        \
        int ph = (c) / nkc;                                                     \
        int kc = ((c) - ph * nkc) * 64;                                         \
        const __nv_bfloat16* Ag = Aps[ph];                                      \
        const __nv_bfloat16* Bg = Bps[ph];                                      \
        _Pragma("unroll")                                                       \
        for (int j = 0; j < 4; j++) {                                           \
            int row = lrow + j * 32;                                            \
            uint32_t doff = (uint32_t)(s) * STAGEB + (row * AST + lhf * 8) * 2; \
            cp_async16(sA + doff, Ag + (size_t)(bm + row) * K + kc + lhf * 8);  \
            cp_async16(sB + doff, Bg + (size_t)(bn + row) * K + kc + lhf * 8);  \
        }                                                                       \
        asm volatile("cp.async.commit_group;" ::: "memory");                    \
    } while (0)

    PREFETCH(0, 0);

    for (int c = 0; c < nch; c++) {
        if (c + 1 < nch) {
            PREFETCH(c + 1, (c + 1) & 1);
            asm volatile("cp.async.wait_group 1;" ::: "memory");
        } else {
            asm volatile("cp.async.wait_group 0;" ::: "memory");
        }
        __syncthreads();

        const uint32_t aBase = sA + (uint32_t)(c & 1) * STAGEB;
        const uint32_t bBase = sB + (uint32_t)(c & 1) * STAGEB;
#pragma unroll
        for (int ks = 0; ks < 4; ks++) {
            const int k0 = ks * 16;
            uint32_t a[4][4], b[4][2];
#pragma unroll
            for (int mf = 0; mf < 4; mf++) {
                int m = wm + mf * 16 + m_l;
                ldsm4(a[mf][0], a[mf][1], a[mf][2], a[mf][3],
                      aBase + (m * AST + k0 + kb_l) * 2);
            }
#pragma unroll
            for (int nf = 0; nf < 4; nf++) {
                int n = wn + nf * 8 + bn_l;
                uint32_t addr = bBase + (n * AST + k0 + bk_l) * 2;
                asm volatile("ld.shared.b32 %0, [%1];" : "=r"(b[nf][0]) : "r"(addr));
                asm volatile("ld.shared.b32 %0, [%1];" : "=r"(b[nf][1]) : "r"(addr + 16));
            }
#pragma unroll
            for (int mf = 0; mf < 4; mf++)
#pragma unroll
                for (int nf = 0; nf < 4; nf++)
                    mma16816(acc[mf][nf], a[mf], b[nf]);
        }
        __syncthreads();
    }
#undef PREFETCH

#pragma unroll
    for (int mf = 0; mf < 4; mf++) {
        int m0 = bm + wm + mf * 16 + (lane >> 2);
#pragma unroll
        for (int nf = 0; nf < 4; nf++) {
            int n0 = bn + wn + nf * 8 + (lane & 3) * 2;
            float bx = 0.f, by = 0.f;
            if (ADD_BIAS) { bx = bias[n0]; by = bias[n0 + 1]; }
            float2 v0 = make_float2(acc[mf][nf][0] + bx, acc[mf][nf][1] + by);
            float2 v1 = make_float2(acc[mf][nf][2] + bx, acc[mf][nf][3] + by);
            *(float2*)&C[(size_t)m0 * N + n0]       = v0;
            *(float2*)&C[(size_t)(m0 + 8) * N + n0] = v1;
        }
    }
}

// ---------------------------------------------------------------------------
// fp32 -> bf16 hi/lo split
// ---------------------------------------------------------------------------
__global__ void split_kernel(const float* __restrict__ x,
                             __nv_bfloat16* __restrict__ hi,
                             __nv_bfloat16* __restrict__ lo, int n4) {
    int i = blockIdx.x * blockDim.x + threadIdx.x;
    if (i < n4) {
        float4 v = ((const float4*)x)[i];
        __nv_bfloat16 h0 = __float2bfloat16(v.x), h1 = __float2bfloat16(v.y);
        __nv_bfloat16 h2 = __float2bfloat16(v.z), h3 = __float2bfloat16(v.w);
        __nv_bfloat16 l0 = __float2bfloat16(v.x - __bfloat162float(h0));
        __nv_bfloat16 l1 = __float2bfloat16(v.y - __bfloat162float(h1));
        __nv_bfloat16 l2 = __float2bfloat16(v.z - __bfloat162float(h2));
        __nv_bfloat16 l3 = __float2bfloat16(v.w - __bfloat162float(h3));
        ((__nv_bfloat162*)hi)[2 * i]     = __halves2bfloat162(h0, h1);
        ((__nv_bfloat162*)hi)[2 * i + 1] = __halves2bfloat162(h2, h3);
        ((__nv_bfloat162*)lo)[2 * i]     = __halves2bfloat162(l0, l1);
        ((__nv_bfloat162*)lo)[2 * i + 1] = __halves2bfloat162(l2, l3);
    }
}

// ---------------------------------------------------------------------------
// bias gather
// ---------------------------------------------------------------------------
__global__ void gather_bias_kernel(const float* __restrict__ bt,
                                   const int* __restrict__ ri,
                                   float* __restrict__ ob) {
    int idx = blockIdx.x * blockDim.x + threadIdx.x;
    if (idx < HEADS * TT * TT) {
        int h = idx / (TT * TT);
        int p = idx - h * (TT * TT);
        ob[idx] = bt[ri[p] * HEADS + h];
    }
}

// ---------------------------------------------------------------------------
// Flash-style fused attention: block = (window, head-pair), 128 threads.
// thread (sub = t>>6 selects head, q = t&63 < 49 selects query row).
// k/v in dynamic smem; q, o in registers; online softmax (no S storage).
// Writes ctx as bf16 hi/lo for the proj GEMM.
// ---------------------------------------------------------------------------
__global__ __launch_bounds__(128)
void win_attn_kernel(const float* __restrict__ qkv,
                     const float* __restrict__ qn_w,
                     const float* __restrict__ kn_w,
                     const float* __restrict__ biasg,
                     __nv_bfloat16* __restrict__ chi,
                     __nv_bfloat16* __restrict__ clo) {
    extern __shared__ float sm[];
    float* ks = sm;                        // [2][TT][KST]
    float* vs = sm + 2 * TT * KST;         // [2][TT][KST]
    __shared__ float nwq[HD], nwk[HD];

    const int b   = blockIdx.x;
    const int hp  = blockIdx.y;            // head pair 0..5
    const int tid = threadIdx.x;
    const int sub = tid >> 6;              // 0/1 -> head 2hp+sub
    const int qi  = tid & 63;
    const int h   = 2 * hp + sub;

    if (tid < HD) { nwq[tid] = qn_w[tid]; nwk[tid] = kn_w[tid]; }

    const float* wbase = qkv + (size_t)b * TT * NQKV;

    // cooperative k/v load: 1568 float4 over 128 threads; 256B contiguous spans
    for (int i = tid; i < 2 * TT * 16; i += 128) {
        int s   = i / (TT * 16);
        int rem = i - s * (TT * 16);
        int r   = rem >> 4;
        int kv  = (rem >> 3) & 1;
        int sg  = rem & 7;
        const float* gp = wbase + (size_t)r * NQKV + DIM * (1 + kv)
                        + (2 * hp + s) * HD + sg * 4;
        float* dst = (kv ? vs : ks) + ((s * TT + r) * KST + sg * 4);
        *(float4*)dst = *(const float4*)gp;
    }
    __syncthreads();

    // k rmsnorm: thread (sub, qi<49) normalizes k row qi of head sub
    if (qi < TT) {
        float* kr = ks + (sub * TT + qi) * KST;
        float ssk = 0.f;
#pragma unroll
        for (int d = 0; d < HD; d++) { float k = kr[d]; ssk += k * k; }
        float rk = rsqrtf(ssk * (1.f / HD) + EPS);
#pragma unroll
        for (int d = 0; d < HD; d++) kr[d] *= rk * nwk[d];
    }

    // q load + rmsnorm (registers)
    float q[HD];
    if (qi < TT) {
        const float* qp = wbase + (size_t)qi * NQKV + h * HD;
        float ssq = 0.f;
#pragma unroll
        for (int dv = 0; dv < 8; dv++) {
            float4 v = *(const float4*)(qp + dv * 4);
            q[dv * 4] = v.x; q[dv * 4 + 1] = v.y;
            q[dv * 4 + 2] = v.z; q[dv * 4 + 3] = v.w;
            ssq += v.x * v.x + v.y * v.y + v.z * v.z + v.w * v.w;
        }
        float rq = rsqrtf(ssq * (1.f / HD) + EPS);
#pragma unroll
        for (int d = 0; d < HD; d++) q[d] = q[d] * rq * nwq[d] * SCALE;
    }
    __syncthreads();   // k-norm complete before cross-row reads

    if (qi < TT) {
        const float* brow = biasg + ((size_t)h * TT + qi) * TT;
        const float* kb = ks + sub * TT * KST;
        const float* vb = vs + sub * TT * KST;

        float m = -1e30f, sum = 0.f;
        float o[HD];
#pragma unroll
        for (int d = 0; d < HD; d++) o[d] = 0.f;

        for (int j = 0; j < TT; j++) {
            const float* kr = kb + j * KST;
            float s = brow[j];
#pragma unroll
            for (int dv = 0; dv < 8; dv++) {
                float4 kk = *(const float4*)(kr + dv * 4);   // broadcast
                s += q[dv * 4]     * kk.x + q[dv * 4 + 1] * kk.y
                   + q[dv * 4 + 2] * kk.z + q[dv * 4 + 3] * kk.w;
            }
            if (s > m) {                       // rare rescale (amortized ~ln49)
                float corr = __expf(m - s);
                sum *= corr;
#pragma unroll
                for (int d = 0; d < HD; d++) o[d] *= corr;
                m = s;
            }
            float p = __expf(s - m);
            sum += p;
            const float* vr = vb + j * KST;
#pragma unroll
            for (int dv = 0; dv < 8; dv++) {
                float4 vv = *(const float4*)(vr + dv * 4);   // broadcast
                o[dv * 4]     += p * vv.x; o[dv * 4 + 1] += p * vv.y;
                o[dv * 4 + 2] += p * vv.z; o[dv * 4 + 3] += p * vv.w;
            }
        }
        float inv = 1.f / sum;

        size_t co = ((size_t)b * TT + qi) * DIM + h * HD;
#pragma unroll
        for (int dv = 0; dv < 16; dv++) {
            float a = o[dv * 2]     * inv;
            float c = o[dv * 2 + 1] * inv;
            __nv_bfloat16 ha = __float2bfloat16(a), hc = __float2bfloat16(c);
            __nv_bfloat16 la = __float2bfloat16(a - __bfloat162float(ha));
            __nv_bfloat16 lc = __float2bfloat16(c - __bfloat162float(hc));
            *(__nv_bfloat162*)(chi + co + dv * 2) = __halves2bfloat162(ha, hc);
            *(__nv_bfloat162*)(clo + co + dv * 2) = __halves2bfloat162(la, lc);
        }
    }
}

// ---------------------------------------------------------------------------
// Launch
// ---------------------------------------------------------------------------
extern "C" void kernel_launch(void* const* d_in, const int* in_sizes, int n_in,
                              void* d_out, int out_size) {
    const float* x          = (const float*)d_in[0];
    const float* qkv_w      = (const float*)d_in[1];
    const float* q_norm_w   = (const float*)d_in[2];
    const float* k_norm_w   = (const float*)d_in[3];
    const float* proj_w     = (const float*)d_in[4];
    const float* proj_b     = (const float*)d_in[5];
    const float* bias_table = (const float*)d_in[6];
    const int*   rel_index  = (const int*)d_in[7];
    float* out = (float*)d_out;

    float *qkvb, *biasb;
    __nv_bfloat16 *xhi, *xlo, *chi, *clo, *whi, *wlo, *phi, *plo;
    cudaGetSymbolAddress((void**)&qkvb,  g_qkv);
    cudaGetSymbolAddress((void**)&biasb, g_biasg);
    cudaGetSymbolAddress((void**)&xhi, g_xhi);  cudaGetSymbolAddress((void**)&xlo, g_xlo);
    cudaGetSymbolAddress((void**)&chi, g_chi);  cudaGetSymbolAddress((void**)&clo, g_clo);
    cudaGetSymbolAddress((void**)&whi, g_whi);  cudaGetSymbolAddress((void**)&wlo, g_wlo);
    cudaGetSymbolAddress((void**)&phi, g_phi);  cudaGetSymbolAddress((void**)&plo, g_plo);

    cudaFuncSetAttribute(gemm_hmma3<false>, cudaFuncAttributeMaxDynamicSharedMemorySize, GEMM_SMEM);
    cudaFuncSetAttribute(gemm_hmma3<true>,  cudaFuncAttributeMaxDynamicSharedMemorySize, GEMM_SMEM);
    cudaFuncSetAttribute(win_attn_kernel,   cudaFuncAttributeMaxDynamicSharedMemorySize, ATT_SMEM);

    // bias gather
    gather_bias_kernel<<<(HEADS * TT * TT + 255) / 256, 256>>>(bias_table, rel_index, biasb);

    // splits
    {
        int n4 = (MROWS * DIM) / 4;
        split_kernel<<<(n4 + 255) / 256, 256>>>(x, xhi, xlo, n4);
        int w4 = (NQKV * DIM) / 4;
        split_kernel<<<(w4 + 255) / 256, 256>>>(qkv_w, whi, wlo, w4);
        int p4 = (DIM * DIM) / 4;
        split_kernel<<<(p4 + 255) / 256, 256>>>(proj_w, phi, plo, p4);
    }

    // qkv = x @ qkv_w^T  (HMMA, 3-product bf16)
    {
        dim3 grid(NQKV / 128, MROWS / 128);
        gemm_hmma3<false><<<grid, 256, GEMM_SMEM>>>(xhi, xlo, whi, wlo, nullptr, qkvb,
                                                    MROWS, NQKV, DIM);
    }

    // fused windowed attention -> ctx (bf16 hi/lo)
    {
        dim3 grid(NWIN, HEADS / 2);
        win_attn_kernel<<<grid, 128, ATT_SMEM>>>(qkvb, q_norm_w, k_norm_w, biasb, chi, clo);
    }

    // out = ctx @ proj_w^T + proj_b
    {
        dim3 grid(DIM / 128, MROWS / 128);
        gemm_hmma3<true><<<grid, 256, GEMM_SMEM>>>(chi, clo, phi, plo, proj_b, out,
                                                   MROWS, DIM, DIM);
    }
}

// round 9
// speedup vs baseline: 1.8598x; 1.8598x over previous
#include <cuda_runtime.h>
#include <cuda_fp16.h>
#include <cstdint>
#include <cstddef>

// Problem constants
#define NWIN   4096
#define TT     49
#define DIM    384
#define HEADS  12
#define HD     32
#define NQKV   1152
#define MROWS  (NWIN * TT)            // 200704
#define SCALE  0.17677669529663687f
#define EPS    1e-6f

#define AST    40                     // smem row stride in fp16 elems (80 B)
#define STAGEB (128 * AST * 2)        // 10240 bytes per stage per operand

// ---------------------------------------------------------------------------
// Scratch (device globals; no allocations allowed)
// ---------------------------------------------------------------------------
__device__ float  g_qkv[(size_t)MROWS * NQKV];   // 925 MB fp32
__device__ __half g_xhi[(size_t)MROWS * DIM];
__device__ __half g_xlo[(size_t)MROWS * DIM];
__device__ __half g_chi[(size_t)MROWS * DIM];
__device__ __half g_clo[(size_t)MROWS * DIM];
__device__ __half g_w16[NQKV * DIM];             // qkv_w rounded to fp16
__device__ __half g_p16[DIM * DIM];              // proj_w rounded to fp16
__device__ float  g_biasg[HEADS * TT * TT];

// ---------------------------------------------------------------------------
// PTX helpers (baseline sm_80+ ISA only — tcgen05 rejected by this toolchain)
// ---------------------------------------------------------------------------
__device__ __forceinline__ uint32_t smem_u32(const void* p) {
    uint32_t a;
    asm("{ .reg .u64 t; cvta.to.shared.u64 t, %1; cvt.u32.u64 %0, t; }"
        : "=r"(a) : "l"(p));
    return a;
}
__device__ __forceinline__ void cp_async16(uint32_t dst, const void* src) {
    asm volatile("cp.async.cg.shared.global [%0], [%1], 16;"
                 :: "r"(dst), "l"(src) : "memory");
}
__device__ __forceinline__ void ldsm4(uint32_t& r0, uint32_t& r1,
                                      uint32_t& r2, uint32_t& r3, uint32_t a) {
    asm volatile("ldmatrix.sync.aligned.m8n8.x4.shared.b16 {%0,%1,%2,%3}, [%4];"
                 : "=r"(r0), "=r"(r1), "=r"(r2), "=r"(r3) : "r"(a));
}
__device__ __forceinline__ void mma16816(float* d, const uint32_t* a,
                                         const uint32_t* b) {
    asm volatile(
        "mma.sync.aligned.m16n8k16.row.col.f32.f16.f16.f32 "
        "{%0,%1,%2,%3}, {%4,%5,%6,%7}, {%8,%9}, {%0,%1,%2,%3};"
        : "+f"(d[0]), "+f"(d[1]), "+f"(d[2]), "+f"(d[3])
        : "r"(a[0]), "r"(a[1]), "r"(a[2]), "r"(a[3]), "r"(b[0]), "r"(b[1]));
}

// ---------------------------------------------------------------------------
// HMMA GEMM: C[M,N] = (Ahi + Alo)[M,K] @ B[N,K]^T (+bias). fp32 accum.
// 2-product fp16 emulation. BM=BN=128, BK=32, 8 warps (2x4), warp tile 64x32.
// Identical structure to the validated R4 kernel (static smem, 2 CTA/SM).
// ---------------------------------------------------------------------------
template<bool ADD_BIAS>
__global__ __launch_bounds__(256, 2)
void gemm_hmma2(const __half* __restrict__ Ah,
                const __half* __restrict__ Al,
                const __half* __restrict__ B,
                const float* __restrict__ bias, float* __restrict__ C,
                int M, int N, int K) {
    __shared__ __half As[2][128 * AST];
    __shared__ __half Bs[2][128 * AST];

    const int tid  = threadIdx.x;
    const int wid  = tid >> 5, lane = tid & 31;
    const int bm   = blockIdx.y * 128, bn = blockIdx.x * 128;
    const int wm   = (wid >> 2) * 64,  wn = (wid & 3) * 32;

    float acc[4][4][4];
#pragma unroll
    for (int i = 0; i < 4; i++)
#pragma unroll
        for (int j = 0; j < 4; j++)
#pragma unroll
            for (int r = 0; r < 4; r++) acc[i][j][r] = 0.f;

    const __half* Aps[2] = {Ah, Al};
    const int nkc = K >> 5;          // 12 for K=384
    const int nch = 2 * nkc;         // 24

    const uint32_t sA = smem_u32(As);
    const uint32_t sB = smem_u32(Bs);

    // loader coords: 2 lines each of A and B per thread
    const int lrow = tid >> 2;       // 0..63
    const int lhf  = tid & 3;        // 0..3 (x8 halves)

    // ldmatrix / B-frag lane coords
    const int m_l  = (lane & 7) + ((lane >> 3) & 1) * 8;
    const int kb_l = (lane >> 4) * 8;
    const int bn_l = lane >> 2;
    const int bk_l = (lane & 3) * 2;

#define PREFETCH(c, s)                                                         \
    do {                                                                       \
        int ph = (c) < nkc ? 0 : 1;                                            \
        int kc = ((c) - ph * nkc) * 32;                                        \
        const __half* Ag = Aps[ph];                                            \
        _Pragma("unroll")                                                      \
        for (int j = 0; j < 2; j++) {                                          \
            int row = lrow + j * 64;                                           \
            uint32_t doff = (uint32_t)(s) * STAGEB + (row * AST + lhf * 8) * 2;\
            cp_async16(sA + doff, Ag + (size_t)(bm + row) * K + kc + lhf * 8); \
            cp_async16(sB + doff, B  + (size_t)(bn + row) * K + kc + lhf * 8); \
        }                                                                      \
        asm volatile("cp.async.commit_group;" ::: "memory");                   \
    } while (0)

    PREFETCH(0, 0);

    for (int c = 0; c < nch; c++) {
        if (c + 1 < nch) {
            PREFETCH(c + 1, (c + 1) & 1);
            asm volatile("cp.async.wait_group 1;" ::: "memory");
        } else {
            asm volatile("cp.async.wait_group 0;" ::: "memory");
        }
        __syncthreads();

        const uint32_t aBase = sA + (uint32_t)(c & 1) * STAGEB;
        const uint32_t bBase = sB + (uint32_t)(c & 1) * STAGEB;
#pragma unroll
        for (int ks = 0; ks < 2; ks++) {
            const int k0 = ks * 16;
            uint32_t a[4][4], b[4][2];
#pragma unroll
            for (int mf = 0; mf < 4; mf++) {
                int m = wm + mf * 16 + m_l;
                ldsm4(a[mf][0], a[mf][1], a[mf][2], a[mf][3],
                      aBase + (m * AST + k0 + kb_l) * 2);
            }
#pragma unroll
            for (int nf = 0; nf < 4; nf++) {
                int n = wn + nf * 8 + bn_l;
                uint32_t addr = bBase + (n * AST + k0 + bk_l) * 2;
                asm volatile("ld.shared.b32 %0, [%1];" : "=r"(b[nf][0]) : "r"(addr));
                asm volatile("ld.shared.b32 %0, [%1];" : "=r"(b[nf][1]) : "r"(addr + 16));
            }
#pragma unroll
            for (int mf = 0; mf < 4; mf++)
#pragma unroll
                for (int nf = 0; nf < 4; nf++)
                    mma16816(acc[mf][nf], a[mf], b[nf]);
        }
        __syncthreads();
    }
#undef PREFETCH

#pragma unroll
    for (int mf = 0; mf < 4; mf++) {
        int m0 = bm + wm + mf * 16 + (lane >> 2);
#pragma unroll
        for (int nf = 0; nf < 4; nf++) {
            int n0 = bn + wn + nf * 8 + (lane & 3) * 2;
            float bx = 0.f, by = 0.f;
            if (ADD_BIAS) { bx = bias[n0]; by = bias[n0 + 1]; }
            float2 v0 = make_float2(acc[mf][nf][0] + bx, acc[mf][nf][1] + by);
            float2 v1 = make_float2(acc[mf][nf][2] + bx, acc[mf][nf][3] + by);
            *(float2*)&C[(size_t)m0 * N + n0]       = v0;
            *(float2*)&C[(size_t)(m0 + 8) * N + n0] = v1;
        }
    }
}

// ---------------------------------------------------------------------------
// fp32 -> fp16 hi/lo split (for x)
// ---------------------------------------------------------------------------
__global__ void split_kernel(const float* __restrict__ x,
                             __half* __restrict__ hi,
                             __half* __restrict__ lo, int n4) {
    int i = blockIdx.x * blockDim.x + threadIdx.x;
    if (i < n4) {
        float4 v = ((const float4*)x)[i];
        __half h0 = __float2half_rn(v.x), h1 = __float2half_rn(v.y);
        __half h2 = __float2half_rn(v.z), h3 = __float2half_rn(v.w);
        __half l0 = __float2half_rn(v.x - __half2float(h0));
        __half l1 = __float2half_rn(v.y - __half2float(h1));
        __half l2 = __float2half_rn(v.z - __half2float(h2));
        __half l3 = __float2half_rn(v.w - __half2float(h3));
        ((__half2*)hi)[2 * i]     = __halves2half2(h0, h1);
        ((__half2*)hi)[2 * i + 1] = __halves2half2(h2, h3);
        ((__half2*)lo)[2 * i]     = __halves2half2(l0, l1);
        ((__half2*)lo)[2 * i + 1] = __halves2half2(l2, l3);
    }
}

// fp32 -> fp16 round (for weights)
__global__ void round_kernel(const float* __restrict__ x,
                             __half* __restrict__ y, int n4) {
    int i = blockIdx.x * blockDim.x + threadIdx.x;
    if (i < n4) {
        float4 v = ((const float4*)x)[i];
        ((__half2*)y)[2 * i]     = __halves2half2(__float2half_rn(v.x), __float2half_rn(v.y));
        ((__half2*)y)[2 * i + 1] = __halves2half2(__float2half_rn(v.z), __float2half_rn(v.w));
    }
}

// ---------------------------------------------------------------------------
// bias gather
// ---------------------------------------------------------------------------
__global__ void gather_bias_kernel(const float* __restrict__ bt,
                                   const int* __restrict__ ri,
                                   float* __restrict__ ob) {
    int idx = blockIdx.x * blockDim.x + threadIdx.x;
    if (idx < HEADS * TT * TT) {
        int h = idx / (TT * TT);
        int p = idx - h * (TT * TT);
        ob[idx] = bt[ri[p] * HEADS + h];
    }
}

// ---------------------------------------------------------------------------
// Fused attention (R4-validated structure): one block per (window, head),
// 64 threads. rmsnorm -> S -> softmax -> S@v. Writes ctx as fp16 hi/lo.
// ---------------------------------------------------------------------------
__global__ __launch_bounds__(64)
void win_attn_kernel(const float* __restrict__ qkv,
                     const float* __restrict__ qn_w,
                     const float* __restrict__ kn_w,
                     const float* __restrict__ biasg,
                     __half* __restrict__ chi,
                     __half* __restrict__ clo) {
    const int b = blockIdx.x;
    const int h = blockIdx.y;
    const int tid = threadIdx.x;

    __shared__ float qs[TT][36];
    __shared__ float ks[TT][36];
    __shared__ float vs[TT][36];
    __shared__ float S[TT][TT];
    __shared__ float nwq[HD], nwk[HD];

    if (tid < HD) { nwq[tid] = qn_w[tid]; nwk[tid] = kn_w[tid]; }

    const float* base = qkv + (size_t)b * TT * NQKV + h * HD;
    for (int v4 = tid; v4 < TT * 8; v4 += 64) {
        int i = v4 >> 3, dv = v4 & 7;
        const float* rp = base + (size_t)i * NQKV + dv * 4;
        *(float4*)&qs[i][dv * 4] = *(const float4*)(rp);
        *(float4*)&ks[i][dv * 4] = *(const float4*)(rp + DIM);
        *(float4*)&vs[i][dv * 4] = *(const float4*)(rp + 2 * DIM);
    }
    __syncthreads();

    float qreg[HD];
    if (tid < TT) {
        float ssq = 0.f, ssk = 0.f;
#pragma unroll
        for (int d = 0; d < HD; d++) {
            float q = qs[tid][d]; qreg[d] = q; ssq += q * q;
            float k = ks[tid][d]; ssk += k * k;
        }
        float rq = rsqrtf(ssq * (1.f / HD) + EPS);
        float rk = rsqrtf(ssk * (1.f / HD) + EPS);
#pragma unroll
        for (int d = 0; d < HD; d++) {
            qreg[d] = qreg[d] * rq * nwq[d];
            ks[tid][d] *= rk * nwk[d];
        }
    }
    __syncthreads();

    if (tid < TT) {
        const float* brow = biasg + ((size_t)h * TT + tid) * TT;
        float mx = -1e30f;
        for (int j = 0; j < TT; j++) {
            float s = 0.f;
#pragma unroll
            for (int dv = 0; dv < 8; dv++) {
                float4 kk = *(const float4*)&ks[j][dv * 4];
                s += qreg[dv * 4]     * kk.x + qreg[dv * 4 + 1] * kk.y
                   + qreg[dv * 4 + 2] * kk.z + qreg[dv * 4 + 3] * kk.w;
            }
            s = s * SCALE + brow[j];
            S[tid][j] = s;
            mx = fmaxf(mx, s);
        }
        float sum = 0.f;
        for (int j = 0; j < TT; j++) {
            float e = __expf(S[tid][j] - mx);
            S[tid][j] = e;
            sum += e;
        }
        float inv = 1.f / sum;

        float o[HD];
#pragma unroll
        for (int d = 0; d < HD; d++) o[d] = 0.f;
        for (int j = 0; j < TT; j++) {
            float p = S[tid][j];
#pragma unroll
            for (int dv = 0; dv < 8; dv++) {
                float4 vv = *(const float4*)&vs[j][dv * 4];
                o[dv * 4]     += p * vv.x; o[dv * 4 + 1] += p * vv.y;
                o[dv * 4 + 2] += p * vv.z; o[dv * 4 + 3] += p * vv.w;
            }
        }
        size_t co = ((size_t)b * TT + tid) * DIM + h * HD;
#pragma unroll
        for (int dv = 0; dv < 16; dv++) {
            float a = o[dv * 2]     * inv;
            float c = o[dv * 2 + 1] * inv;
            __half ha = __float2half_rn(a), hc = __float2half_rn(c);
            __half la = __float2half_rn(a - __half2float(ha));
            __half lc = __float2half_rn(c - __half2float(hc));
            *(__half2*)(chi + co + dv * 2) = __halves2half2(ha, hc);
            *(__half2*)(clo + co + dv * 2) = __halves2half2(la, lc);
        }
    }
}

// ---------------------------------------------------------------------------
// Launch
// ---------------------------------------------------------------------------
extern "C" void kernel_launch(void* const* d_in, const int* in_sizes, int n_in,
                              void* d_out, int out_size) {
    const float* x          = (const float*)d_in[0];
    const float* qkv_w      = (const float*)d_in[1];
    const float* q_norm_w   = (const float*)d_in[2];
    const float* k_norm_w   = (const float*)d_in[3];
    const float* proj_w     = (const float*)d_in[4];
    const float* proj_b     = (const float*)d_in[5];
    const float* bias_table = (const float*)d_in[6];
    const int*   rel_index  = (const int*)d_in[7];
    float* out = (float*)d_out;

    float *qkvb, *biasb;
    __half *xhi, *xlo, *chi, *clo, *w16, *p16;
    cudaGetSymbolAddress((void**)&qkvb,  g_qkv);
    cudaGetSymbolAddress((void**)&biasb, g_biasg);
    cudaGetSymbolAddress((void**)&xhi, g_xhi);  cudaGetSymbolAddress((void**)&xlo, g_xlo);
    cudaGetSymbolAddress((void**)&chi, g_chi);  cudaGetSymbolAddress((void**)&clo, g_clo);
    cudaGetSymbolAddress((void**)&w16, g_w16);  cudaGetSymbolAddress((void**)&p16, g_p16);

    // bias gather
    gather_bias_kernel<<<(HEADS * TT * TT + 255) / 256, 256>>>(bias_table, rel_index, biasb);

    // splits / rounds
    {
        int n4 = (MROWS * DIM) / 4;
        split_kernel<<<(n4 + 255) / 256, 256>>>(x, xhi, xlo, n4);
        int w4 = (NQKV * DIM) / 4;
        round_kernel<<<(w4 + 255) / 256, 256>>>(qkv_w, w16, w4);
        int p4 = (DIM * DIM) / 4;
        round_kernel<<<(p4 + 255) / 256, 256>>>(proj_w, p16, p4);
    }

    // qkv = x @ qkv_w^T  (HMMA, 2-product fp16)
    {
        dim3 grid(NQKV / 128, MROWS / 128);
        gemm_hmma2<false><<<grid, 256>>>(xhi, xlo, w16, nullptr, qkvb,
                                         MROWS, NQKV, DIM);
    }

    // fused windowed attention -> ctx (fp16 hi/lo)
    {
        dim3 grid(NWIN, HEADS);
        win_attn_kernel<<<grid, 64>>>(qkvb, q_norm_w, k_norm_w, biasb, chi, clo);
    }

    // out = ctx @ proj_w^T + proj_b
    {
        dim3 grid(DIM / 128, MROWS / 128);
        gemm_hmma2<true><<<grid, 256>>>(chi, clo, p16, proj_b, out,
                                        MROWS, DIM, DIM);
    }
}

// round 10
// speedup vs baseline: 2.7600x; 1.4840x over previous
#include <cuda_runtime.h>
#include <cuda_fp16.h>
#include <cstdint>
#include <cstddef>

// Problem constants
#define NWIN   4096
#define TT     49
#define DIM    384
#define HEADS  12
#define HD     32
#define NQKV   1152
#define MROWS  (NWIN * TT)            // 200704
#define SCALE  0.17677669529663687f
#define EPS    1e-6f

#define AST    40                     // smem row stride in fp16 elems (80 B)
#define STAGEB (128 * AST * 2)        // 10240 bytes per stage per operand

// ---------------------------------------------------------------------------
// Scratch (device globals; no allocations allowed)
// ---------------------------------------------------------------------------
__device__ float  g_qkv[(size_t)MROWS * NQKV];   // 925 MB fp32
__device__ __half g_x16[(size_t)MROWS * DIM];
__device__ __half g_c16[(size_t)MROWS * DIM];
__device__ __half g_w16[NQKV * DIM];             // qkv_w rounded to fp16
__device__ __half g_p16[DIM * DIM];              // proj_w rounded to fp16
__device__ float  g_biasg[HEADS * TT * TT];

// ---------------------------------------------------------------------------
// PTX helpers (baseline sm_80+ ISA only — tcgen05 rejected by this toolchain)
// ---------------------------------------------------------------------------
__device__ __forceinline__ uint32_t smem_u32(const void* p) {
    uint32_t a;
    asm("{ .reg .u64 t; cvta.to.shared.u64 t, %1; cvt.u32.u64 %0, t; }"
        : "=r"(a) : "l"(p));
    return a;
}
__device__ __forceinline__ void cp_async16(uint32_t dst, const void* src) {
    asm volatile("cp.async.cg.shared.global [%0], [%1], 16;"
                 :: "r"(dst), "l"(src) : "memory");
}
__device__ __forceinline__ void ldsm4(uint32_t& r0, uint32_t& r1,
                                      uint32_t& r2, uint32_t& r3, uint32_t a) {
    asm volatile("ldmatrix.sync.aligned.m8n8.x4.shared.b16 {%0,%1,%2,%3}, [%4];"
                 : "=r"(r0), "=r"(r1), "=r"(r2), "=r"(r3) : "r"(a));
}
__device__ __forceinline__ void mma16816(float* d, const uint32_t* a,
                                         const uint32_t* b) {
    asm volatile(
        "mma.sync.aligned.m16n8k16.row.col.f32.f16.f16.f32 "
        "{%0,%1,%2,%3}, {%4,%5,%6,%7}, {%8,%9}, {%0,%1,%2,%3};"
        : "+f"(d[0]), "+f"(d[1]), "+f"(d[2]), "+f"(d[3])
        : "r"(a[0]), "r"(a[1]), "r"(a[2]), "r"(a[3]), "r"(b[0]), "r"(b[1]));
}

// ---------------------------------------------------------------------------
// HMMA GEMM: C[M,N] = A[M,K] @ B[N,K]^T (+bias). fp16 in, fp32 accum.
// BM=BN=128, BK=32, 8 warps (2x4), warp tile 64x32, m16n8k16.
// Structure identical to the validated R4/R9 kernel (static smem, 2 CTA/SM).
// ---------------------------------------------------------------------------
template<bool ADD_BIAS>
__global__ __launch_bounds__(256, 2)
void gemm_hmma1(const __half* __restrict__ A,
                const __half* __restrict__ B,
                const float* __restrict__ bias, float* __restrict__ C,
                int M, int N, int K) {
    __shared__ __half As[2][128 * AST];
    __shared__ __half Bs[2][128 * AST];

    const int tid  = threadIdx.x;
    const int wid  = tid >> 5, lane = tid & 31;
    const int bm   = blockIdx.y * 128, bn = blockIdx.x * 128;
    const int wm   = (wid >> 2) * 64,  wn = (wid & 3) * 32;

    float acc[4][4][4];
#pragma unroll
    for (int i = 0; i < 4; i++)
#pragma unroll
        for (int j = 0; j < 4; j++)
#pragma unroll
            for (int r = 0; r < 4; r++) acc[i][j][r] = 0.f;

    const int nch = K >> 5;          // 12 for K=384

    const uint32_t sA = smem_u32(As);
    const uint32_t sB = smem_u32(Bs);

    // loader coords: 2 lines each of A and B per thread
    const int lrow = tid >> 2;       // 0..63
    const int lhf  = tid & 3;        // 0..3 (x8 halves)

    // ldmatrix / B-frag lane coords
    const int m_l  = (lane & 7) + ((lane >> 3) & 1) * 8;
    const int kb_l = (lane >> 4) * 8;
    const int bn_l = lane >> 2;
    const int bk_l = (lane & 3) * 2;

#define PREFETCH(c, s)                                                         \
    do {                                                                       \
        int kc = (c) * 32;                                                     \
        _Pragma("unroll")                                                      \
        for (int j = 0; j < 2; j++) {                                          \
            int row = lrow + j * 64;                                           \
            uint32_t doff = (uint32_t)(s) * STAGEB + (row * AST + lhf * 8) * 2;\
            cp_async16(sA + doff, A + (size_t)(bm + row) * K + kc + lhf * 8);  \
            cp_async16(sB + doff, B + (size_t)(bn + row) * K + kc + lhf * 8);  \
        }                                                                      \
        asm volatile("cp.async.commit_group;" ::: "memory");                   \
    } while (0)

    PREFETCH(0, 0);

    for (int c = 0; c < nch; c++) {
        if (c + 1 < nch) {
            PREFETCH(c + 1, (c + 1) & 1);
            asm volatile("cp.async.wait_group 1;" ::: "memory");
        } else {
            asm volatile("cp.async.wait_group 0;" ::: "memory");
        }
        __syncthreads();

        const uint32_t aBase = sA + (uint32_t)(c & 1) * STAGEB;
        const uint32_t bBase = sB + (uint32_t)(c & 1) * STAGEB;
#pragma unroll
        for (int ks = 0; ks < 2; ks++) {
            const int k0 = ks * 16;
            uint32_t a[4][4], b[4][2];
#pragma unroll
            for (int mf = 0; mf < 4; mf++) {
                int m = wm + mf * 16 + m_l;
                ldsm4(a[mf][0], a[mf][1], a[mf][2], a[mf][3],
                      aBase + (m * AST + k0 + kb_l) * 2);
            }
#pragma unroll
            for (int nf = 0; nf < 4; nf++) {
                int n = wn + nf * 8 + bn_l;
                uint32_t addr = bBase + (n * AST + k0 + bk_l) * 2;
                asm volatile("ld.shared.b32 %0, [%1];" : "=r"(b[nf][0]) : "r"(addr));
                asm volatile("ld.shared.b32 %0, [%1];" : "=r"(b[nf][1]) : "r"(addr + 16));
            }
#pragma unroll
            for (int mf = 0; mf < 4; mf++)
#pragma unroll
                for (int nf = 0; nf < 4; nf++)
                    mma16816(acc[mf][nf], a[mf], b[nf]);
        }
        __syncthreads();
    }
#undef PREFETCH

#pragma unroll
    for (int mf = 0; mf < 4; mf++) {
        int m0 = bm + wm + mf * 16 + (lane >> 2);
#pragma unroll
        for (int nf = 0; nf < 4; nf++) {
            int n0 = bn + wn + nf * 8 + (lane & 3) * 2;
            float bx = 0.f, by = 0.f;
            if (ADD_BIAS) { bx = bias[n0]; by = bias[n0 + 1]; }
            float2 v0 = make_float2(acc[mf][nf][0] + bx, acc[mf][nf][1] + by);
            float2 v1 = make_float2(acc[mf][nf][2] + bx, acc[mf][nf][3] + by);
            *(float2*)&C[(size_t)m0 * N + n0]       = v0;
            *(float2*)&C[(size_t)(m0 + 8) * N + n0] = v1;
        }
    }
}

// ---------------------------------------------------------------------------
// fp32 -> fp16 round
// ---------------------------------------------------------------------------
__global__ void round_kernel(const float* __restrict__ x,
                             __half* __restrict__ y, int n4) {
    int i = blockIdx.x * blockDim.x + threadIdx.x;
    if (i < n4) {
        float4 v = ((const float4*)x)[i];
        ((__half2*)y)[2 * i]     = __halves2half2(__float2half_rn(v.x), __float2half_rn(v.y));
        ((__half2*)y)[2 * i + 1] = __halves2half2(__float2half_rn(v.z), __float2half_rn(v.w));
    }
}

// ---------------------------------------------------------------------------
// bias gather
// ---------------------------------------------------------------------------
__global__ void gather_bias_kernel(const float* __restrict__ bt,
                                   const int* __restrict__ ri,
                                   float* __restrict__ ob) {
    int idx = blockIdx.x * blockDim.x + threadIdx.x;
    if (idx < HEADS * TT * TT) {
        int h = idx / (TT * TT);
        int p = idx - h * (TT * TT);
        ob[idx] = bt[ri[p] * HEADS + h];
    }
}

// ---------------------------------------------------------------------------
// Fused attention (validated structure): one block per (window, head),
// 64 threads. rmsnorm -> S -> softmax -> S@v. Writes ctx as fp16.
// ---------------------------------------------------------------------------
__global__ __launch_bounds__(64)
void win_attn_kernel(const float* __restrict__ qkv,
                     const float* __restrict__ qn_w,
                     const float* __restrict__ kn_w,
                     const float* __restrict__ biasg,
                     __half* __restrict__ c16) {
    const int b = blockIdx.x;
    const int h = blockIdx.y;
    const int tid = threadIdx.x;

    __shared__ float qs[TT][36];
    __shared__ float ks[TT][36];
    __shared__ float vs[TT][36];
    __shared__ float S[TT][TT];
    __shared__ float nwq[HD], nwk[HD];

    if (tid < HD) { nwq[tid] = qn_w[tid]; nwk[tid] = kn_w[tid]; }

    const float* base = qkv + (size_t)b * TT * NQKV + h * HD;
    for (int v4 = tid; v4 < TT * 8; v4 += 64) {
        int i = v4 >> 3, dv = v4 & 7;
        const float* rp = base + (size_t)i * NQKV + dv * 4;
        *(float4*)&qs[i][dv * 4] = *(const float4*)(rp);
        *(float4*)&ks[i][dv * 4] = *(const float4*)(rp + DIM);
        *(float4*)&vs[i][dv * 4] = *(const float4*)(rp + 2 * DIM);
    }
    __syncthreads();

    float qreg[HD];
    if (tid < TT) {
        float ssq = 0.f, ssk = 0.f;
#pragma unroll
        for (int d = 0; d < HD; d++) {
            float q = qs[tid][d]; qreg[d] = q; ssq += q * q;
            float k = ks[tid][d]; ssk += k * k;
        }
        float rq = rsqrtf(ssq * (1.f / HD) + EPS);
        float rk = rsqrtf(ssk * (1.f / HD) + EPS);
#pragma unroll
        for (int d = 0; d < HD; d++) {
            qreg[d] = qreg[d] * rq * nwq[d];
            ks[tid][d] *= rk * nwk[d];
        }
    }
    __syncthreads();

    if (tid < TT) {
        const float* brow = biasg + ((size_t)h * TT + tid) * TT;
        float mx = -1e30f;
        for (int j = 0; j < TT; j++) {
            float s = 0.f;
#pragma unroll
            for (int dv = 0; dv < 8; dv++) {
                float4 kk = *(const float4*)&ks[j][dv * 4];
                s += qreg[dv * 4]     * kk.x + qreg[dv * 4 + 1] * kk.y
                   + qreg[dv * 4 + 2] * kk.z + qreg[dv * 4 + 3] * kk.w;
            }
            s = s * SCALE + brow[j];
            S[tid][j] = s;
            mx = fmaxf(mx, s);
        }
        float sum = 0.f;
        for (int j = 0; j < TT; j++) {
            float e = __expf(S[tid][j] - mx);
            S[tid][j] = e;
            sum += e;
        }
        float inv = 1.f / sum;

        float o[HD];
#pragma unroll
        for (int d = 0; d < HD; d++) o[d] = 0.f;
        for (int j = 0; j < TT; j++) {
            float p = S[tid][j];
#pragma unroll
            for (int dv = 0; dv < 8; dv++) {
                float4 vv = *(const float4*)&vs[j][dv * 4];
                o[dv * 4]     += p * vv.x; o[dv * 4 + 1] += p * vv.y;
                o[dv * 4 + 2] += p * vv.z; o[dv * 4 + 3] += p * vv.w;
            }
        }
        size_t co = ((size_t)b * TT + tid) * DIM + h * HD;
#pragma unroll
        for (int dv = 0; dv < 16; dv++) {
            *(__half2*)(c16 + co + dv * 2) =
                __halves2half2(__float2half_rn(o[dv * 2] * inv),
                               __float2half_rn(o[dv * 2 + 1] * inv));
        }
    }
}

// ---------------------------------------------------------------------------
// Launch
// ---------------------------------------------------------------------------
extern "C" void kernel_launch(void* const* d_in, const int* in_sizes, int n_in,
                              void* d_out, int out_size) {
    const float* x          = (const float*)d_in[0];
    const float* qkv_w      = (const float*)d_in[1];
    const float* q_norm_w   = (const float*)d_in[2];
    const float* k_norm_w   = (const float*)d_in[3];
    const float* proj_w     = (const float*)d_in[4];
    const float* proj_b     = (const float*)d_in[5];
    const float* bias_table = (const float*)d_in[6];
    const int*   rel_index  = (const int*)d_in[7];
    float* out = (float*)d_out;

    float *qkvb, *biasb;
    __half *x16, *c16, *w16, *p16;
    cudaGetSymbolAddress((void**)&qkvb,  g_qkv);
    cudaGetSymbolAddress((void**)&biasb, g_biasg);
    cudaGetSymbolAddress((void**)&x16, g_x16);
    cudaGetSymbolAddress((void**)&c16, g_c16);
    cudaGetSymbolAddress((void**)&w16, g_w16);
    cudaGetSymbolAddress((void**)&p16, g_p16);

    // bias gather
    gather_bias_kernel<<<(HEADS * TT * TT + 255) / 256, 256>>>(bias_table, rel_index, biasb);

    // fp16 rounds
    {
        int n4 = (MROWS * DIM) / 4;
        round_kernel<<<(n4 + 255) / 256, 256>>>(x, x16, n4);
        int w4 = (NQKV * DIM) / 4;
        round_kernel<<<(w4 + 255) / 256, 256>>>(qkv_w, w16, w4);
        int p4 = (DIM * DIM) / 4;
        round_kernel<<<(p4 + 255) / 256, 256>>>(proj_w, p16, p4);
    }

    // qkv = x @ qkv_w^T  (HMMA fp16 single product)
    {
        dim3 grid(NQKV / 128, MROWS / 128);
        gemm_hmma1<false><<<grid, 256>>>(x16, w16, nullptr, qkvb,
                                         MROWS, NQKV, DIM);
    }

    // fused windowed attention -> ctx (fp16)
    {
        dim3 grid(NWIN, HEADS);
        win_attn_kernel<<<grid, 64>>>(qkvb, q_norm_w, k_norm_w, biasb, c16);
    }

    // out = ctx @ proj_w^T + proj_b
    {
        dim3 grid(DIM / 128, MROWS / 128);
        gemm_hmma1<true><<<grid, 256>>>(c16, p16, proj_b, out,
                                        MROWS, DIM, DIM);
    }
}

// round 13
// speedup vs baseline: 2.7922x; 1.0117x over previous
#include <cuda_runtime.h>
#include <cuda_fp16.h>
#include <cstdint>
#include <cstddef>

// Problem constants
#define NWIN   4096
#define TT     49
#define DIM    384
#define HEADS  12
#define HD     32
#define NQKV   1152
#define MROWS  (NWIN * TT)            // 200704
#define SCALE  0.17677669529663687f
#define EPS    1e-6f

#define AST    40                     // smem row stride in fp16 elems (80 B)
#define STAGEB (128 * AST * 2)        // 10240 bytes per stage per operand

// ---------------------------------------------------------------------------
// Scratch (device globals; no allocations allowed)
// ---------------------------------------------------------------------------
__device__ float  g_qkv[(size_t)MROWS * NQKV];   // 925 MB fp32
__device__ __half g_x16[(size_t)MROWS * DIM];
__device__ __half g_c16[(size_t)MROWS * DIM];
__device__ __half g_w16[NQKV * DIM];             // qkv_w rounded to fp16
__device__ __half g_p16[DIM * DIM];              // proj_w rounded to fp16
__device__ float  g_biasg[HEADS * TT * TT];

// ---------------------------------------------------------------------------
// PTX helpers (baseline sm_80+/sm_100-family ISA; NO tcgen05 on this toolchain)
// ---------------------------------------------------------------------------
__device__ __forceinline__ uint32_t smem_u32(const void* p) {
    uint32_t a;
    asm("{ .reg .u64 t; cvta.to.shared.u64 t, %1; cvt.u32.u64 %0, t; }"
        : "=r"(a) : "l"(p));
    return a;
}
__device__ __forceinline__ void cp_async16(uint32_t dst, const void* src) {
    asm volatile("cp.async.cg.shared.global [%0], [%1], 16;"
                 :: "r"(dst), "l"(src) : "memory");
}
__device__ __forceinline__ void ldsm4(uint32_t& r0, uint32_t& r1,
                                      uint32_t& r2, uint32_t& r3, uint32_t a) {
    asm volatile("ldmatrix.sync.aligned.m8n8.x4.shared.b16 {%0,%1,%2,%3}, [%4];"
                 : "=r"(r0), "=r"(r1), "=r"(r2), "=r"(r3) : "r"(a));
}
__device__ __forceinline__ void mma16816(float* d, const uint32_t* a,
                                         const uint32_t* b) {
    asm volatile(
        "mma.sync.aligned.m16n8k16.row.col.f32.f16.f16.f32 "
        "{%0,%1,%2,%3}, {%4,%5,%6,%7}, {%8,%9}, {%0,%1,%2,%3};"
        : "+f"(d[0]), "+f"(d[1]), "+f"(d[2]), "+f"(d[3])
        : "r"(a[0]), "r"(a[1]), "r"(a[2]), "r"(a[3]), "r"(b[0]), "r"(b[1]));
}
// packed fp32x2 FMA (sm_100 family): d = a*b + c, 2 lanes per instruction
__device__ __forceinline__ uint64_t fma2(uint64_t a, uint64_t b, uint64_t c) {
    uint64_t d;
    asm("fma.rn.f32x2 %0, %1, %2, %3;" : "=l"(d) : "l"(a), "l"(b), "l"(c));
    return d;
}
__device__ __forceinline__ uint64_t pack2(float lo, float hi) {
    uint64_t d;
    asm("mov.b64 %0, {%1, %2};" : "=l"(d) : "f"(lo), "f"(hi));
    return d;
}
__device__ __forceinline__ float2 unpack2(uint64_t v) {
    float2 r;
    asm("mov.b64 {%0, %1}, %2;" : "=f"(r.x), "=f"(r.y) : "l"(v));
    return r;
}
// 16B shared load as two packed f32x2 operands
__device__ __forceinline__ void lds_2x64(uint64_t& a, uint64_t& b, uint32_t addr) {
    asm volatile("ld.shared.v2.u64 {%0, %1}, [%2];" : "=l"(a), "=l"(b) : "r"(addr));
}

// ---------------------------------------------------------------------------
// HMMA GEMM: C[M,N] = A[M,K] @ B[N,K]^T (+bias). fp16 in, fp32 accum.
// BM=BN=128, BK=32, 8 warps (2x4), warp tile 64x32, m16n8k16.
// (validated R10 kernel — unchanged)
// ---------------------------------------------------------------------------
template<bool ADD_BIAS>
__global__ __launch_bounds__(256, 2)
void gemm_hmma1(const __half* __restrict__ A,
                const __half* __restrict__ B,
                const float* __restrict__ bias, float* __restrict__ C,
                int M, int N, int K) {
    __shared__ __half As[2][128 * AST];
    __shared__ __half Bs[2][128 * AST];

    const int tid  = threadIdx.x;
    const int wid  = tid >> 5, lane = tid & 31;
    const int bm   = blockIdx.y * 128, bn = blockIdx.x * 128;
    const int wm   = (wid >> 2) * 64,  wn = (wid & 3) * 32;

    float acc[4][4][4];
#pragma unroll
    for (int i = 0; i < 4; i++)
#pragma unroll
        for (int j = 0; j < 4; j++)
#pragma unroll
            for (int r = 0; r < 4; r++) acc[i][j][r] = 0.f;

    const int nch = K >> 5;          // 12 for K=384

    const uint32_t sA = smem_u32(As);
    const uint32_t sB = smem_u32(Bs);

    const int lrow = tid >> 2;       // 0..63
    const int lhf  = tid & 3;        // 0..3 (x8 halves)

    const int m_l  = (lane & 7) + ((lane >> 3) & 1) * 8;
    const int kb_l = (lane >> 4) * 8;
    const int bn_l = lane >> 2;
    const int bk_l = (lane & 3) * 2;

#define PREFETCH(c, s)                                                         \
    do {                                                                       \
        int kc = (c) * 32;                                                     \
        _Pragma("unroll")                                                      \
        for (int j = 0; j < 2; j++) {                                          \
            int row = lrow + j * 64;                                           \
            uint32_t doff = (uint32_t)(s) * STAGEB + (row * AST + lhf * 8) * 2;\
            cp_async16(sA + doff, A + (size_t)(bm + row) * K + kc + lhf * 8);  \
            cp_async16(sB + doff, B + (size_t)(bn + row) * K + kc + lhf * 8);  \
        }                                                                      \
        asm volatile("cp.async.commit_group;" ::: "memory");                   \
    } while (0)

    PREFETCH(0, 0);

    for (int c = 0; c < nch; c++) {
        if (c + 1 < nch) {
            PREFETCH(c + 1, (c + 1) & 1);
            asm volatile("cp.async.wait_group 1;" ::: "memory");
        } else {
            asm volatile("cp.async.wait_group 0;" ::: "memory");
        }
        __syncthreads();

        const uint32_t aBase = sA + (uint32_t)(c & 1) * STAGEB;
        const uint32_t bBase = sB + (uint32_t)(c & 1) * STAGEB;
#pragma unroll
        for (int ks = 0; ks < 2; ks++) {
            const int k0 = ks * 16;
            uint32_t a[4][4], b[4][2];
#pragma unroll
            for (int mf = 0; mf < 4; mf++) {
                int m = wm + mf * 16 + m_l;
                ldsm4(a[mf][0], a[mf][1], a[mf][2], a[mf][3],
                      aBase + (m * AST + k0 + kb_l) * 2);
            }
#pragma unroll
            for (int nf = 0; nf < 4; nf++) {
                int n = wn + nf * 8 + bn_l;
                uint32_t addr = bBase + (n * AST + k0 + bk_l) * 2;
                asm volatile("ld.shared.b32 %0, [%1];" : "=r"(b[nf][0]) : "r"(addr));
                asm volatile("ld.shared.b32 %0, [%1];" : "=r"(b[nf][1]) : "r"(addr + 16));
            }
#pragma unroll
            for (int mf = 0; mf < 4; mf++)
#pragma unroll
                for (int nf = 0; nf < 4; nf++)
                    mma16816(acc[mf][nf], a[mf], b[nf]);
        }
        __syncthreads();
    }
#undef PREFETCH

#pragma unroll
    for (int mf = 0; mf < 4; mf++) {
        int m0 = bm + wm + mf * 16 + (lane >> 2);
#pragma unroll
        for (int nf = 0; nf < 4; nf++) {
            int n0 = bn + wn + nf * 8 + (lane & 3) * 2;
            float bx = 0.f, by = 0.f;
            if (ADD_BIAS) { bx = bias[n0]; by = bias[n0 + 1]; }
            float2 v0 = make_float2(acc[mf][nf][0] + bx, acc[mf][nf][1] + by);
            float2 v1 = make_float2(acc[mf][nf][2] + bx, acc[mf][nf][3] + by);
            *(float2*)&C[(size_t)m0 * N + n0]       = v0;
            *(float2*)&C[(size_t)(m0 + 8) * N + n0] = v1;
        }
    }
}

// ---------------------------------------------------------------------------
// fp32 -> fp16 round
// ---------------------------------------------------------------------------
__global__ void round_kernel(const float* __restrict__ x,
                             __half* __restrict__ y, int n4) {
    int i = blockIdx.x * blockDim.x + threadIdx.x;
    if (i < n4) {
        float4 v = ((const float4*)x)[i];
        ((__half2*)y)[2 * i]     = __halves2half2(__float2half_rn(v.x), __float2half_rn(v.y));
        ((__half2*)y)[2 * i + 1] = __halves2half2(__float2half_rn(v.z), __float2half_rn(v.w));
    }
}

// ---------------------------------------------------------------------------
// bias gather
// ---------------------------------------------------------------------------
__global__ void gather_bias_kernel(const float* __restrict__ bt,
                                   const int* __restrict__ ri,
                                   float* __restrict__ ob) {
    int idx = blockIdx.x * blockDim.x + threadIdx.x;
    if (idx < HEADS * TT * TT) {
        int h = idx / (TT * TT);
        int p = idx - h * (TT * TT);
        ob[idx] = bt[ri[p] * HEADS + h];
    }
}

// ---------------------------------------------------------------------------
// Fused attention: one block per (window, head), 64 threads.
// rmsnorm -> S -> softmax -> S@v. Inner loops use packed fma.rn.f32x2
// (exact fp32, half the FMA-class issue count). Writes ctx as fp16.
// ---------------------------------------------------------------------------
__global__ __launch_bounds__(64)
void win_attn_kernel(const float* __restrict__ qkv,
                     const float* __restrict__ qn_w,
                     const float* __restrict__ kn_w,
                     const float* __restrict__ biasg,
                     __half* __restrict__ c16) {
    const int b = blockIdx.x;
    const int h = blockIdx.y;
    const int tid = threadIdx.x;

    __shared__ float qs[TT][36];
    __shared__ float ks[TT][36];
    __shared__ float vs[TT][36];
    __shared__ float S[TT][TT];
    __shared__ float nwq[HD], nwk[HD];

    if (tid < HD) { nwq[tid] = qn_w[tid]; nwk[tid] = kn_w[tid]; }

    const float* base = qkv + (size_t)b * TT * NQKV + h * HD;
    for (int v4 = tid; v4 < TT * 8; v4 += 64) {
        int i = v4 >> 3, dv = v4 & 7;
        const float* rp = base + (size_t)i * NQKV + dv * 4;
        *(float4*)&qs[i][dv * 4] = *(const float4*)(rp);
        *(float4*)&ks[i][dv * 4] = *(const float4*)(rp + DIM);
        *(float4*)&vs[i][dv * 4] = *(const float4*)(rp + 2 * DIM);
    }
    __syncthreads();

    uint64_t q2[16];                 // q packed as 16 f32x2 pairs (SCALE folded)
    if (tid < TT) {
        float qreg[HD];
        float ssq = 0.f, ssk = 0.f;
#pragma unroll
        for (int d = 0; d < HD; d++) {
            float q = qs[tid][d]; qreg[d] = q; ssq += q * q;
            float k = ks[tid][d]; ssk += k * k;
        }
        float rq = rsqrtf(ssq * (1.f / HD) + EPS) * SCALE;
        float rk = rsqrtf(ssk * (1.f / HD) + EPS);
#pragma unroll
        for (int d = 0; d < HD; d++) {
            qreg[d] = qreg[d] * rq * nwq[d];
            ks[tid][d] *= rk * nwk[d];
        }
#pragma unroll
        for (int p = 0; p < 16; p++)
            q2[p] = pack2(qreg[2 * p], qreg[2 * p + 1]);
    }
    __syncthreads();   // all k rows normalized before cross-row reads

    if (tid < TT) {
        const float* brow = biasg + ((size_t)h * TT + tid) * TT;
        const uint32_t ksb = smem_u32(ks);
        const uint32_t vsb = smem_u32(vs);

        float mx = -1e30f;
        for (int j = 0; j < TT; j++) {
            uint64_t acc0 = 0ull, acc1 = 0ull;   // two f32x2 chains (0.0f pairs)
            uint32_t kr = ksb + (uint32_t)(j * 36 * 4);
#pragma unroll
            for (int dv = 0; dv < 8; dv++) {
                uint64_t ka, kb;
                lds_2x64(ka, kb, kr + dv * 16);
                acc0 = fma2(q2[2 * dv],     ka, acc0);
                acc1 = fma2(q2[2 * dv + 1], kb, acc1);
            }
            float2 a0 = unpack2(acc0), a1 = unpack2(acc1);
            float s = (a0.x + a0.y) + (a1.x + a1.y) + brow[j];
            S[tid][j] = s;
            mx = fmaxf(mx, s);
        }
        float sum = 0.f;
        for (int j = 0; j < TT; j++) {
            float e = __expf(S[tid][j] - mx);
            S[tid][j] = e;
            sum += e;
        }
        float inv = 1.f / sum;

        uint64_t o2[16];
#pragma unroll
        for (int p = 0; p < 16; p++) o2[p] = 0ull;
        for (int j = 0; j < TT; j++) {
            float p = S[tid][j];
            uint64_t pp = pack2(p, p);
            uint32_t vr = vsb + (uint32_t)(j * 36 * 4);
#pragma unroll
            for (int dv = 0; dv < 8; dv++) {
                uint64_t va, vb;
                lds_2x64(va, vb, vr + dv * 16);
                o2[2 * dv]     = fma2(pp, va, o2[2 * dv]);
                o2[2 * dv + 1] = fma2(pp, vb, o2[2 * dv + 1]);
            }
        }

        size_t co = ((size_t)b * TT + tid) * DIM + h * HD;
#pragma unroll
        for (int p = 0; p < 16; p++) {
            float2 o = unpack2(o2[p]);
            *(__half2*)(c16 + co + p * 2) =
                __halves2half2(__float2half_rn(o.x * inv),
                               __float2half_rn(o.y * inv));
        }
    }
}

// ---------------------------------------------------------------------------
// Launch
// ---------------------------------------------------------------------------
extern "C" void kernel_launch(void* const* d_in, const int* in_sizes, int n_in,
                              void* d_out, int out_size) {
    const float* x          = (const float*)d_in[0];
    const float* qkv_w      = (const float*)d_in[1];
    const float* q_norm_w   = (const float*)d_in[2];
    const float* k_norm_w   = (const float*)d_in[3];
    const float* proj_w     = (const float*)d_in[4];
    const float* proj_b     = (const float*)d_in[5];
    const float* bias_table = (const float*)d_in[6];
    const int*   rel_index  = (const int*)d_in[7];
    float* out = (float*)d_out;

    float *qkvb, *biasb;
    __half *x16, *c16, *w16, *p16;
    cudaGetSymbolAddress((void**)&qkvb,  g_qkv);
    cudaGetSymbolAddress((void**)&biasb, g_biasg);
    cudaGetSymbolAddress((void**)&x16, g_x16);
    cudaGetSymbolAddress((void**)&c16, g_c16);
    cudaGetSymbolAddress((void**)&w16, g_w16);
    cudaGetSymbolAddress((void**)&p16, g_p16);

    // bias gather
    gather_bias_kernel<<<(HEADS * TT * TT + 255) / 256, 256>>>(bias_table, rel_index, biasb);

    // fp16 rounds
    {
        int n4 = (MROWS * DIM) / 4;
        round_kernel<<<(n4 + 255) / 256, 256>>>(x, x16, n4);
        int w4 = (NQKV * DIM) / 4;
        round_kernel<<<(w4 + 255) / 256, 256>>>(qkv_w, w16, w4);
        int p4 = (DIM * DIM) / 4;
        round_kernel<<<(p4 + 255) / 256, 256>>>(proj_w, p16, p4);
    }

    // qkv = x @ qkv_w^T  (HMMA fp16 single product)
    {
        dim3 grid(NQKV / 128, MROWS / 128);
        gemm_hmma1<false><<<grid, 256>>>(x16, w16, nullptr, qkvb,
                                         MROWS, NQKV, DIM);
    }

    // fused windowed attention -> ctx (fp16)
    {
        dim3 grid(NWIN, HEADS);
        win_attn_kernel<<<grid, 64>>>(qkvb, q_norm_w, k_norm_w, biasb, c16);
    }

    // out = ctx @ proj_w^T + proj_b
    {
        dim3 grid(DIM / 128, MROWS / 128);
        gemm_hmma1<true><<<grid, 256>>>(c16, p16, proj_b, out,
                                        MROWS, DIM, DIM);
    }
}

// round 15
// speedup vs baseline: 2.8048x; 1.0045x over previous
#include <cuda_runtime.h>
#include <cuda_fp16.h>
#include <cstdint>
#include <cstddef>

// Problem constants
#define NWIN   4096
#define TT     49
#define DIM    384
#define HEADS  12
#define HD     32
#define NQKV   1152
#define MROWS  (NWIN * TT)            // 200704
#define SCALE  0.17677669529663687f
#define EPS    1e-6f

#define AST    40                     // smem row stride in fp16 elems (80 B)
#define STAGEB (128 * AST * 2)        // 10240 bytes per stage per operand

// ---------------------------------------------------------------------------
// Scratch (device globals; no allocations allowed)
// ---------------------------------------------------------------------------
__device__ __half g_qkv16[(size_t)MROWS * NQKV]; // 462 MB fp16 intermediate
__device__ __half g_x16[(size_t)MROWS * DIM];
__device__ __half g_c16[(size_t)MROWS * DIM];
__device__ __half g_w16[NQKV * DIM];             // qkv_w rounded to fp16
__device__ __half g_p16[DIM * DIM];              // proj_w rounded to fp16
__device__ float  g_biasg[HEADS * TT * TT];

// ---------------------------------------------------------------------------
// PTX helpers (baseline sm_80+/sm_100-family ISA; NO tcgen05 on this toolchain)
// ---------------------------------------------------------------------------
__device__ __forceinline__ uint32_t smem_u32(const void* p) {
    uint32_t a;
    asm("{ .reg .u64 t; cvta.to.shared.u64 t, %1; cvt.u32.u64 %0, t; }"
        : "=r"(a) : "l"(p));
    return a;
}
__device__ __forceinline__ void cp_async16(uint32_t dst, const void* src) {
    asm volatile("cp.async.cg.shared.global [%0], [%1], 16;"
                 :: "r"(dst), "l"(src) : "memory");
}
__device__ __forceinline__ void ldsm4(uint32_t& r0, uint32_t& r1,
                                      uint32_t& r2, uint32_t& r3, uint32_t a) {
    asm volatile("ldmatrix.sync.aligned.m8n8.x4.shared.b16 {%0,%1,%2,%3}, [%4];"
                 : "=r"(r0), "=r"(r1), "=r"(r2), "=r"(r3) : "r"(a));
}
__device__ __forceinline__ void mma16816(float* d, const uint32_t* a,
                                         const uint32_t* b) {
    asm volatile(
        "mma.sync.aligned.m16n8k16.row.col.f32.f16.f16.f32 "
        "{%0,%1,%2,%3}, {%4,%5,%6,%7}, {%8,%9}, {%0,%1,%2,%3};"
        : "+f"(d[0]), "+f"(d[1]), "+f"(d[2]), "+f"(d[3])
        : "r"(a[0]), "r"(a[1]), "r"(a[2]), "r"(a[3]), "r"(b[0]), "r"(b[1]));
}
// packed fp32x2 FMA (sm_100 family)
__device__ __forceinline__ uint64_t fma2(uint64_t a, uint64_t b, uint64_t c) {
    uint64_t d;
    asm("fma.rn.f32x2 %0, %1, %2, %3;" : "=l"(d) : "l"(a), "l"(b), "l"(c));
    return d;
}
__device__ __forceinline__ uint64_t pack2(float lo, float hi) {
    uint64_t d;
    asm("mov.b64 %0, {%1, %2};" : "=l"(d) : "f"(lo), "f"(hi));
    return d;
}
__device__ __forceinline__ float2 unpack2(uint64_t v) {
    float2 r;
    asm("mov.b64 {%0, %1}, %2;" : "=f"(r.x), "=f"(r.y) : "l"(v));
    return r;
}
__device__ __forceinline__ void lds_2x64(uint64_t& a, uint64_t& b, uint32_t addr) {
    asm volatile("ld.shared.v2.u64 {%0, %1}, [%2];" : "=l"(a), "=l"(b) : "r"(addr));
}

// ---------------------------------------------------------------------------
// HMMA GEMM: C[M,N] = A[M,K] @ B[N,K]^T (+bias). fp16 in, fp32 accum.
// BM=BN=128, BK=32, 8 warps (2x4), warp tile 64x32, m16n8k16.
// OUT_HALF: store C as fp16 (half2 stores) — used for the qkv intermediate.
// ---------------------------------------------------------------------------
template<bool ADD_BIAS, bool OUT_HALF>
__global__ __launch_bounds__(256, 2)
void gemm_hmma1(const __half* __restrict__ A,
                const __half* __restrict__ B,
                const float* __restrict__ bias, void* __restrict__ Cv,
                int M, int N, int K) {
    __shared__ __half As[2][128 * AST];
    __shared__ __half Bs[2][128 * AST];

    const int tid  = threadIdx.x;
    const int wid  = tid >> 5, lane = tid & 31;
    const int bm   = blockIdx.y * 128, bn = blockIdx.x * 128;
    const int wm   = (wid >> 2) * 64,  wn = (wid & 3) * 32;

    float acc[4][4][4];
#pragma unroll
    for (int i = 0; i < 4; i++)
#pragma unroll
        for (int j = 0; j < 4; j++)
#pragma unroll
            for (int r = 0; r < 4; r++) acc[i][j][r] = 0.f;

    const int nch = K >> 5;          // 12 for K=384

    const uint32_t sA = smem_u32(As);
    const uint32_t sB = smem_u32(Bs);

    const int lrow = tid >> 2;       // 0..63
    const int lhf  = tid & 3;        // 0..3 (x8 halves)

    const int m_l  = (lane & 7) + ((lane >> 3) & 1) * 8;
    const int kb_l = (lane >> 4) * 8;
    const int bn_l = lane >> 2;
    const int bk_l = (lane & 3) * 2;

#define PREFETCH(c, s)                                                         \
    do {                                                                       \
        int kc = (c) * 32;                                                     \
        _Pragma("unroll")                                                      \
        for (int j = 0; j < 2; j++) {                                          \
            int row = lrow + j * 64;                                           \
            uint32_t doff = (uint32_t)(s) * STAGEB + (row * AST + lhf * 8) * 2;\
            cp_async16(sA + doff, A + (size_t)(bm + row) * K + kc + lhf * 8);  \
            cp_async16(sB + doff, B + (size_t)(bn + row) * K + kc + lhf * 8);  \
        }                                                                      \
        asm volatile("cp.async.commit_group;" ::: "memory");                   \
    } while (0)

    PREFETCH(0, 0);

    for (int c = 0; c < nch; c++) {
        if (c + 1 < nch) {
            PREFETCH(c + 1, (c + 1) & 1);
            asm volatile("cp.async.wait_group 1;" ::: "memory");
        } else {
            asm volatile("cp.async.wait_group 0;" ::: "memory");
        }
        __syncthreads();

        const uint32_t aBase = sA + (uint32_t)(c & 1) * STAGEB;
        const uint32_t bBase = sB + (uint32_t)(c & 1) * STAGEB;
#pragma unroll
        for (int ks = 0; ks < 2; ks++) {
            const int k0 = ks * 16;
            uint32_t a[4][4], b[4][2];
#pragma unroll
            for (int mf = 0; mf < 4; mf++) {
                int m = wm + mf * 16 + m_l;
                ldsm4(a[mf][0], a[mf][1], a[mf][2], a[mf][3],
                      aBase + (m * AST + k0 + kb_l) * 2);
            }
#pragma unroll
            for (int nf = 0; nf < 4; nf++) {
                int n = wn + nf * 8 + bn_l;
                uint32_t addr = bBase + (n * AST + k0 + bk_l) * 2;
                asm volatile("ld.shared.b32 %0, [%1];" : "=r"(b[nf][0]) : "r"(addr));
                asm volatile("ld.shared.b32 %0, [%1];" : "=r"(b[nf][1]) : "r"(addr + 16));
            }
#pragma unroll
            for (int mf = 0; mf < 4; mf++)
#pragma unroll
                for (int nf = 0; nf < 4; nf++)
                    mma16816(acc[mf][nf], a[mf], b[nf]);
        }
        __syncthreads();
    }
#undef PREFETCH

#pragma unroll
    for (int mf = 0; mf < 4; mf++) {
        int m0 = bm + wm + mf * 16 + (lane >> 2);
#pragma unroll
        for (int nf = 0; nf < 4; nf++) {
            int n0 = bn + wn + nf * 8 + (lane & 3) * 2;
            float bx = 0.f, by = 0.f;
            if (ADD_BIAS) { bx = bias[n0]; by = bias[n0 + 1]; }
            float2 v0 = make_float2(acc[mf][nf][0] + bx, acc[mf][nf][1] + by);
            float2 v1 = make_float2(acc[mf][nf][2] + bx, acc[mf][nf][3] + by);
            if (OUT_HALF) {
                __half* C = (__half*)Cv;
                *(__half2*)&C[(size_t)m0 * N + n0] =
                    __halves2half2(__float2half_rn(v0.x), __float2half_rn(v0.y));
                *(__half2*)&C[(size_t)(m0 + 8) * N + n0] =
                    __halves2half2(__float2half_rn(v1.x), __float2half_rn(v1.y));
            } else {
                float* C = (float*)Cv;
                *(float2*)&C[(size_t)m0 * N + n0]       = v0;
                *(float2*)&C[(size_t)(m0 + 8) * N + n0] = v1;
            }
        }
    }
}

// ---------------------------------------------------------------------------
// fp32 -> fp16 round
// ---------------------------------------------------------------------------
__global__ void round_kernel(const float* __restrict__ x,
                             __half* __restrict__ y, int n4) {
    int i = blockIdx.x * blockDim.x + threadIdx.x;
    if (i < n4) {
        float4 v = ((const float4*)x)[i];
        ((__half2*)y)[2 * i]     = __halves2half2(__float2half_rn(v.x), __float2half_rn(v.y));
        ((__half2*)y)[2 * i + 1] = __halves2half2(__float2half_rn(v.z), __float2half_rn(v.w));
    }
}

// ---------------------------------------------------------------------------
// bias gather
// ---------------------------------------------------------------------------
__global__ void gather_bias_kernel(const float* __restrict__ bt,
                                   const int* __restrict__ ri,
                                   float* __restrict__ ob) {
    int idx = blockIdx.x * blockDim.x + threadIdx.x;
    if (idx < HEADS * TT * TT) {
        int h = idx / (TT * TT);
        int p = idx - h * (TT * TT);
        ob[idx] = bt[ri[p] * HEADS + h];
    }
}

// ---------------------------------------------------------------------------
// Fused attention: one block per (window, head), 64 threads.
// qkv read as fp16 (half traffic), converted to fp32 smem; compute fp32.
// rmsnorm -> S -> softmax -> S@v (f32x2 packed). Writes ctx as fp16.
// ---------------------------------------------------------------------------
__global__ __launch_bounds__(64)
void win_attn_kernel(const __half* __restrict__ qkv,
                     const float* __restrict__ qn_w,
                     const float* __restrict__ kn_w,
                     const float* __restrict__ biasg,
                     __half* __restrict__ c16) {
    const int b = blockIdx.x;
    const int h = blockIdx.y;
    const int tid = threadIdx.x;

    __shared__ float qs[TT][36];
    __shared__ float ks[TT][36];
    __shared__ float vs[TT][36];
    __shared__ float S[TT][TT];
    __shared__ float nwq[HD], nwk[HD];

    if (tid < HD) { nwq[tid] = qn_w[tid]; nwk[tid] = kn_w[tid]; }

    const __half* base = qkv + (size_t)b * TT * NQKV + h * HD;
    // 49 rows x 4 x (8 halves) per matrix: 16B global loads (coalesced pairs)
    for (int v4 = tid; v4 < TT * 4; v4 += 64) {
        int i = v4 >> 2, dv = v4 & 3;
        const __half* rp = base + (size_t)i * NQKV + dv * 8;
#pragma unroll
        for (int m = 0; m < 3; m++) {
            uint4 raw = *(const uint4*)(rp + m * DIM);
            float* dst = (m == 0 ? &qs[i][dv * 8] : m == 1 ? &ks[i][dv * 8]
                                                          : &vs[i][dv * 8]);
            __half2* hp = (__half2*)&raw;
#pragma unroll
            for (int p = 0; p < 4; p++) {
                float2 f = __half22float2(hp[p]);
                dst[2 * p] = f.x; dst[2 * p + 1] = f.y;
            }
        }
    }
    __syncthreads();

    uint64_t q2[16];                 // q packed as 16 f32x2 pairs (SCALE folded)
    if (tid < TT) {
        float qreg[HD];
        float ssq = 0.f, ssk = 0.f;
#pragma unroll
        for (int d = 0; d < HD; d++) {
            float q = qs[tid][d]; qreg[d] = q; ssq += q * q;
            float k = ks[tid][d]; ssk += k * k;
        }
        float rq = rsqrtf(ssq * (1.f / HD) + EPS) * SCALE;
        float rk = rsqrtf(ssk * (1.f / HD) + EPS);
#pragma unroll
        for (int d = 0; d < HD; d++) {
            qreg[d] = qreg[d] * rq * nwq[d];
            ks[tid][d] *= rk * nwk[d];
        }
#pragma unroll
        for (int p = 0; p < 16; p++)
            q2[p] = pack2(qreg[2 * p], qreg[2 * p + 1]);
    }
    __syncthreads();   // all k rows normalized before cross-row reads

    if (tid < TT) {
        const float* brow = biasg + ((size_t)h * TT + tid) * TT;
        const uint32_t ksb = smem_u32(ks);
        const uint32_t vsb = smem_u32(vs);

        float mx = -1e30f;
        for (int j = 0; j < TT; j++) {
            uint64_t acc0 = 0ull, acc1 = 0ull;
            uint32_t kr = ksb + (uint32_t)(j * 36 * 4);
#pragma unroll
            for (int dv = 0; dv < 8; dv++) {
                uint64_t ka, kb;
                lds_2x64(ka, kb, kr + dv * 16);
                acc0 = fma2(q2[2 * dv],     ka, acc0);
                acc1 = fma2(q2[2 * dv + 1], kb, acc1);
            }
            float2 a0 = unpack2(acc0), a1 = unpack2(acc1);
            float s = (a0.x + a0.y) + (a1.x + a1.y) + brow[j];
            S[tid][j] = s;
            mx = fmaxf(mx, s);
        }
        float sum = 0.f;
        for (int j = 0; j < TT; j++) {
            float e = __expf(S[tid][j] - mx);
            S[tid][j] = e;
            sum += e;
        }
        float inv = 1.f / sum;

        uint64_t o2[16];
#pragma unroll
        for (int p = 0; p < 16; p++) o2[p] = 0ull;
        for (int j = 0; j < TT; j++) {
            float p = S[tid][j];
            uint64_t pp = pack2(p, p);
            uint32_t vr = vsb + (uint32_t)(j * 36 * 4);
#pragma unroll
            for (int dv = 0; dv < 8; dv++) {
                uint64_t va, vb;
                lds_2x64(va, vb, vr + dv * 16);
                o2[2 * dv]     = fma2(pp, va, o2[2 * dv]);
                o2[2 * dv + 1] = fma2(pp, vb, o2[2 * dv + 1]);
            }
        }

        size_t co = ((size_t)b * TT + tid) * DIM + h * HD;
#pragma unroll
        for (int p = 0; p < 16; p++) {
            float2 o = unpack2(o2[p]);
            *(__half2*)(c16 + co + p * 2) =
                __halves2half2(__float2half_rn(o.x * inv),
                               __float2half_rn(o.y * inv));
        }
    }
}

// ---------------------------------------------------------------------------
// Launch
// ---------------------------------------------------------------------------
extern "C" void kernel_launch(void* const* d_in, const int* in_sizes, int n_in,
                              void* d_out, int out_size) {
    const float* x          = (const float*)d_in[0];
    const float* qkv_w      = (const float*)d_in[1];
    const float* q_norm_w   = (const float*)d_in[2];
    const float* k_norm_w   = (const float*)d_in[3];
    const float* proj_w     = (const float*)d_in[4];
    const float* proj_b     = (const float*)d_in[5];
    const float* bias_table = (const float*)d_in[6];
    const int*   rel_index  = (const int*)d_in[7];
    float* out = (float*)d_out;

    float *biasb;
    __half *qkv16, *x16, *c16, *w16, *p16;
    cudaGetSymbolAddress((void**)&qkv16, g_qkv16);
    cudaGetSymbolAddress((void**)&biasb, g_biasg);
    cudaGetSymbolAddress((void**)&x16, g_x16);
    cudaGetSymbolAddress((void**)&c16, g_c16);
    cudaGetSymbolAddress((void**)&w16, g_w16);
    cudaGetSymbolAddress((void**)&p16, g_p16);

    // bias gather
    gather_bias_kernel<<<(HEADS * TT * TT + 255) / 256, 256>>>(bias_table, rel_index, biasb);

    // fp16 rounds
    {
        int n4 = (MROWS * DIM) / 4;
        round_kernel<<<(n4 + 255) / 256, 256>>>(x, x16, n4);
        int w4 = (NQKV * DIM) / 4;
        round_kernel<<<(w4 + 255) / 256, 256>>>(qkv_w, w16, w4);
        int p4 = (DIM * DIM) / 4;
        round_kernel<<<(p4 + 255) / 256, 256>>>(proj_w, p16, p4);
    }

    // qkv = x @ qkv_w^T  (HMMA fp16, fp16 output)
    {
        dim3 grid(NQKV / 128, MROWS / 128);
        gemm_hmma1<false, true><<<grid, 256>>>(x16, w16, nullptr, qkv16,
                                               MROWS, NQKV, DIM);
    }

    // fused windowed attention -> ctx (fp16)
    {
        dim3 grid(NWIN, HEADS);
        win_attn_kernel<<<grid, 64>>>(qkv16, q_norm_w, k_norm_w, biasb, c16);
    }

    // out = ctx @ proj_w^T + proj_b  (fp32 output to d_out)
    {
        dim3 grid(DIM / 128, MROWS / 128);
        gemm_hmma1<true, false><<<grid, 256>>>(c16, p16, proj_b, out,
                                               MROWS, DIM, DIM);
    }
}